// round 9
// baseline (speedup 1.0000x reference)
#include <cuda_runtime.h>
#include <cuda_bf16.h>
#include <mma.h>
#include <cstdint>

using namespace nvcuda;

// DynamicConv: B=64, CIN=COUT=256, K=4 experts, 3x3 kernel on (L=1024 x 1).
// Width==1 + padding 1 => only kw=1 column contributes: per-batch GEMM
//   C[o,h] = sum_{ci,kh} Wagg[b][o,ci,kh] * x[b][ci,h-1+kh]   (M=256,N=1024,K=768)
// wmma bf16 (HMMA), 3-pass hi/lo split, fp32 accumulate.
// R8: cp.async double-buffered A + direct-from-global B build (no x_s),
//     2 CTAs/SM retained (110 KB smem each).

#define BATCH   64
#define CIN     256
#define COUT    256
#define CS      256
#define KEXP    4
#define HIDDEN  64
#define LEN     1024
#define TEMP    30.0f

#define TM      128            // o per CTA
#define TN      128            // h per CTA
#define CCH     64             // ci per K-chunk
#define NCB     (CIN / CCH)    // 4
#define NTILE   (3 * NCB)      // 12 A tiles per CTA

#define ASTR    72             // bf16 A row stride (144 B rows)
#define BSTR    72             // bf16 B row stride
#define BBSTR   24             // bias tile stride

// SMEM layout (bytes)
#define SM_A0    0                      // A buf0: hi 18432 + lo 18432
#define SM_A1    36864                  // A buf1
#define SM_B     73728                  // B: hi 19584 + lo 19584 (136 rows x 72)
#define SM_BHSZ  19584
#define SM_TOTAL (73728 + 2 * 19584)    // 112896
// bias tiles overlay the B region (used before mainloop only)
#define SM_ABH   SM_B
#define SM_ABL   (SM_B + 6144)
#define SM_BB    (SM_B + 12288)

__device__ float g_att[BATCH * KEXP];
__device__ float g_bmix[BATCH * COUT];
// Wagg bf16 split: [b][kh][cbi][o(256)][ci(64)]
#define WA_BSTRIDE (3 * NCB * COUT * CCH)   // 196608
__device__ __nv_bfloat16 g_wa_hi[BATCH * WA_BSTRIDE];
__device__ __nv_bfloat16 g_wa_lo[BATCH * WA_BSTRIDE];

__device__ __forceinline__ uint32_t smem_u32(const void* p) {
    uint32_t a;
    asm("{ .reg .u64 t; cvta.to.shared.u64 t, %1; cvt.u32.u64 %0, t; }" : "=r"(a) : "l"(p));
    return a;
}
__device__ __forceinline__ void cpa16(uint32_t d, const void* s) {
    asm volatile("cp.async.cg.shared.global [%0], [%1], 16;" :: "r"(d), "l"(s));
}

// ---------------------------------------------------------------------------
// Kernel 1: routing MLP + softmax + mixed bias. 64 blocks x 256 threads.
// ---------------------------------------------------------------------------
__global__ void routing_kernel(const float* __restrict__ cond,
                               const float* __restrict__ w1,
                               const float* __restrict__ w2,
                               const float* __restrict__ bias) {
    __shared__ float sh[HIDDEN];
    __shared__ float sl[KEXP];
    __shared__ float satt[KEXP];
    const int b = blockIdx.x;
    const int t = threadIdx.x;

    if (t < HIDDEN) {
        const float4* crow = (const float4*)(cond + b * CS);
        const float4* w1r  = (const float4*)(w1 + t * CS);
        float s0 = 0.0f, s1 = 0.0f;
#pragma unroll 8
        for (int i = 0; i < CS / 4; ++i) {
            float4 c4 = crow[i], w4 = w1r[i];
            s0 = fmaf(c4.x, w4.x, fmaf(c4.y, w4.y, s0));
            s1 = fmaf(c4.z, w4.z, fmaf(c4.w, w4.w, s1));
        }
        sh[t] = fmaxf(s0 + s1, 0.0f);
    }
    __syncthreads();
    if (t < KEXP) {
        const float* w2r = w2 + t * HIDDEN;
        float s = 0.0f;
#pragma unroll 8
        for (int i = 0; i < HIDDEN; ++i) s = fmaf(sh[i], w2r[i], s);
        sl[t] = s * (1.0f / TEMP);
    }
    __syncthreads();
    if (t == 0) {
        float m = sl[0];
#pragma unroll
        for (int k = 1; k < KEXP; ++k) m = fmaxf(m, sl[k]);
        float e[KEXP], sum = 0.0f;
#pragma unroll
        for (int k = 0; k < KEXP; ++k) { e[k] = expf(sl[k] - m); sum += e[k]; }
        float inv = 1.0f / sum;
#pragma unroll
        for (int k = 0; k < KEXP; ++k) {
            satt[k] = e[k] * inv;
            g_att[b * KEXP + k] = e[k] * inv;
        }
    }
    __syncthreads();
    {   // mixed bias, o = t
        float v = 0.0f;
#pragma unroll
        for (int k = 0; k < KEXP; ++k) v = fmaf(satt[k], bias[k * COUT + t], v);
        g_bmix[b * COUT + t] = v;
    }
}

// ---------------------------------------------------------------------------
// Kernel 2: mix experts + bf16 hi/lo split -> g_wa_hi/lo[b][kh][cbi][o][ci]
// ---------------------------------------------------------------------------
__global__ void mix_kernel(const float* __restrict__ weight) {
    const int idx = blockIdx.x * 256 + threadIdx.x;
    const int ci  = idx & 63;
    const int o   = (idx >> 6) & 255;
    const int cbi = (idx >> 14) & 3;
    const int kh  = idx >> 16;
    const int cig = cbi * CCH + ci;

    float w4[KEXP];
#pragma unroll
    for (int k = 0; k < KEXP; ++k)
        w4[k] = weight[(((k * COUT + o) * CIN + cig) * 3 + kh) * 3 + 1];

    const size_t obase = (((size_t)kh * NCB + cbi) * COUT + o) * CCH + ci;
    for (int b = 0; b < BATCH; ++b) {
        const float* a = g_att + b * KEXP;
        float v = a[0] * w4[0] + a[1] * w4[1] + a[2] * w4[2] + a[3] * w4[3];
        __nv_bfloat16 h = __float2bfloat16(v);
        g_wa_hi[(size_t)b * WA_BSTRIDE + obase] = h;
        g_wa_lo[(size_t)b * WA_BSTRIDE + obase] =
            __float2bfloat16(v - __bfloat162float(h));
    }
}

// ---------------------------------------------------------------------------
// Kernel 3: wmma conv. grid (8 h-tiles, 2 o-tiles, 64 b), 256 threads.
// ---------------------------------------------------------------------------
__global__ void __launch_bounds__(256, 2)
conv_kernel(const float* __restrict__ x, float* __restrict__ out) {
    extern __shared__ char smem[];
    const uint32_t sb = smem_u32(smem);
    const int tid = threadIdx.x;
    const int wid = tid >> 5;
    const int lid = tid & 31;
    const int hb  = blockIdx.x * TN;
    const int ob  = blockIdx.y * TM;
    const int b   = blockIdx.z;
    const int wm  = wid >> 1;     // 0..3 -> 32 o-rows
    const int wn  = wid & 1;      // 0..1 -> 64 h-cols

    const float* xb = x + (size_t)b * CIN * LEN;

    // ---- issue cp.async for A tile 0 (cbi=0, kh=0) into buf0 ----
    auto issue_A = [&](int j, uint32_t bufoff) {
        const int cbi = j >> 2 == 0 ? j / 3 : j / 3;   // j/3
        const int kh  = j - 3 * (j / 3);
        const uint4* gh = (const uint4*)(g_wa_hi +
            ((((size_t)b * 3 + kh) * NCB + (j / 3)) * COUT + ob) * CCH);
        const uint4* gl = (const uint4*)(g_wa_lo +
            ((((size_t)b * 3 + kh) * NCB + (j / 3)) * COUT + ob) * CCH);
        (void)cbi; (void)kh;
#pragma unroll
        for (int t = 0; t < 4; ++t) {
            int idx = tid + t * 256;          // 0..1023 (16B units)
            int r = idx >> 3, c = idx & 7;
            uint32_t d = sb + bufoff + r * 144 + c * 16;
            cpa16(d,         gh + idx);
            cpa16(d + 18432, gl + idx);
        }
        asm volatile("cp.async.commit_group;" ::: "memory");
    };
    issue_A(0, SM_A0);

    // ---- accumulators ----
    wmma::fragment<wmma::accumulator, 16, 16, 16, float> acc[2][4];
#pragma unroll
    for (int mt = 0; mt < 2; ++mt)
#pragma unroll
        for (int nt = 0; nt < 4; ++nt) wmma::fill_fragment(acc[mt][nt], 0.0f);

    // ---- bias via K=16 GEMM term (tiles overlay B region) ----
    for (int i = tid; i < (3 * 6144) / 4; i += 256)
        ((uint32_t*)(smem + SM_ABH))[i] = 0;
    __syncthreads();
    if (tid < 128) {
        float bm = g_bmix[b * COUT + ob + tid];
        __nv_bfloat16 h = __float2bfloat16(bm);
        ((__nv_bfloat16*)(smem + SM_ABH))[tid * BBSTR] = h;
        ((__nv_bfloat16*)(smem + SM_ABL))[tid * BBSTR] =
            __float2bfloat16(bm - __bfloat162float(h));
        ((__nv_bfloat16*)(smem + SM_BB ))[tid * BBSTR] = __float2bfloat16(1.0f);
    }
    __syncthreads();
    {
        wmma::fragment<wmma::matrix_a, 16, 16, 16, __nv_bfloat16, wmma::row_major> fa;
        wmma::fragment<wmma::matrix_b, 16, 16, 16, __nv_bfloat16, wmma::col_major> fb[4];
#pragma unroll
        for (int nt = 0; nt < 4; ++nt)
            wmma::load_matrix_sync(fb[nt],
                (const __nv_bfloat16*)(smem + SM_BB) + (wn * 64 + nt * 16) * BBSTR, BBSTR);
#pragma unroll
        for (int mt = 0; mt < 2; ++mt) {
            wmma::load_matrix_sync(fa,
                (const __nv_bfloat16*)(smem + SM_ABH) + (wm * 32 + mt * 16) * BBSTR, BBSTR);
#pragma unroll
            for (int nt = 0; nt < 4; ++nt) wmma::mma_sync(acc[mt][nt], fa, fb[nt], acc[mt][nt]);
            wmma::load_matrix_sync(fa,
                (const __nv_bfloat16*)(smem + SM_ABL) + (wm * 32 + mt * 16) * BBSTR, BBSTR);
#pragma unroll
            for (int nt = 0; nt < 4; ++nt) wmma::mma_sync(acc[mt][nt], fa, fb[nt], acc[mt][nt]);
        }
    }
    __syncthreads();   // bias tiles dead -> B region reusable

    // ---- mainloop over 12 (cbi, kh) tiles ----
    for (int j = 0; j < NTILE; ++j) {
        const int cbi = j / 3;
        const int kh  = j - 3 * cbi;

        // prefetch next A tile into the other buffer (free since j-1's barrier)
        if (j + 1 < NTILE) {
            issue_A(j + 1, (j + 1) & 1 ? SM_A1 : SM_A0);
        } else {
            asm volatile("cp.async.commit_group;" ::: "memory");  // keep count uniform
        }

        // build B for this cbi (kh==0 only; shared across 3 kh via row offset)
        if (kh == 0) {
            // lane -> (nl = lane>>2, cl = lane&3); warp job covers 8 n x 4 ci-pairs
            const int nl = lid >> 2, cl = lid & 3;
            for (int job = wid; job < 8 * 17; job += 8) {
                const int cpb  = job / 17;
                const int nblk = job - 17 * cpb;
                const int n  = nblk * 8 + nl;
                const int cp = cpb * 4 + cl;        // ci pair 0..31
                if (n < 130) {
                    const int hs = hb - 1 + n;
                    float v0 = 0.0f, v1 = 0.0f;
                    if ((unsigned)hs < (unsigned)LEN) {
                        v0 = xb[(cbi * CCH + 2 * cp    ) * LEN + hs];
                        v1 = xb[(cbi * CCH + 2 * cp + 1) * LEN + hs];
                    }
                    __nv_bfloat16 h0 = __float2bfloat16(v0);
                    __nv_bfloat16 h1 = __float2bfloat16(v1);
                    __nv_bfloat162 hh; hh.x = h0; hh.y = h1;
                    __nv_bfloat162 ll;
                    ll.x = __float2bfloat16(v0 - __bfloat162float(h0));
                    ll.y = __float2bfloat16(v1 - __bfloat162float(h1));
                    *(__nv_bfloat162*)(smem + SM_B + n * 144 + cp * 4) = hh;
                    *(__nv_bfloat162*)(smem + SM_B + SM_BHSZ + n * 144 + cp * 4) = ll;
                }
            }
        }

        asm volatile("cp.async.wait_group 1;" ::: "memory");   // tile j resident
        __syncthreads();

        const char* ab = smem + ((j & 1) ? SM_A1 : SM_A0);
        const __nv_bfloat16* Ah = (const __nv_bfloat16*)(ab);
        const __nv_bfloat16* Al = (const __nv_bfloat16*)(ab + 18432);
        const __nv_bfloat16* Bh = (const __nv_bfloat16*)(smem + SM_B);
        const __nv_bfloat16* Bl = (const __nv_bfloat16*)(smem + SM_B + SM_BHSZ);

#pragma unroll
        for (int ks = 0; ks < 4; ++ks) {
            wmma::fragment<wmma::matrix_a, 16, 16, 16, __nv_bfloat16, wmma::row_major> fah[2], fal[2];
            wmma::fragment<wmma::matrix_b, 16, 16, 16, __nv_bfloat16, wmma::col_major> fbx[4];
#pragma unroll
            for (int mt = 0; mt < 2; ++mt)
                wmma::load_matrix_sync(fah[mt], Ah + (wm * 32 + mt * 16) * ASTR + ks * 16, ASTR);
            // pass 1: Ah * Bh
#pragma unroll
            for (int nt = 0; nt < 4; ++nt)
                wmma::load_matrix_sync(fbx[nt], Bh + (wn * 64 + nt * 16 + kh) * BSTR + ks * 16, BSTR);
#pragma unroll
            for (int mt = 0; mt < 2; ++mt)
#pragma unroll
                for (int nt = 0; nt < 4; ++nt)
                    wmma::mma_sync(acc[mt][nt], fah[mt], fbx[nt], acc[mt][nt]);
            // pass 2: Al * Bh
#pragma unroll
            for (int mt = 0; mt < 2; ++mt)
                wmma::load_matrix_sync(fal[mt], Al + (wm * 32 + mt * 16) * ASTR + ks * 16, ASTR);
#pragma unroll
            for (int mt = 0; mt < 2; ++mt)
#pragma unroll
                for (int nt = 0; nt < 4; ++nt)
                    wmma::mma_sync(acc[mt][nt], fal[mt], fbx[nt], acc[mt][nt]);
            // pass 3: Ah * Bl
#pragma unroll
            for (int nt = 0; nt < 4; ++nt)
                wmma::load_matrix_sync(fbx[nt], Bl + (wn * 64 + nt * 16 + kh) * BSTR + ks * 16, BSTR);
#pragma unroll
            for (int mt = 0; mt < 2; ++mt)
#pragma unroll
                for (int nt = 0; nt < 4; ++nt)
                    wmma::mma_sync(acc[mt][nt], fah[mt], fbx[nt], acc[mt][nt]);
        }
        __syncthreads();   // frag loads done: A buf reusable at j+2, B at next cbi
    }

    // ---- epilogue: bias already in acc; direct global store ----
    float* op = out + ((size_t)(b * COUT + ob + wm * 32)) * LEN + hb + wn * 64;
#pragma unroll
    for (int mt = 0; mt < 2; ++mt)
#pragma unroll
        for (int nt = 0; nt < 4; ++nt)
            wmma::store_matrix_sync(op + (size_t)mt * 16 * LEN + nt * 16,
                                    acc[mt][nt], LEN, wmma::mem_row_major);
}

// ---------------------------------------------------------------------------
extern "C" void kernel_launch(void* const* d_in, const int* in_sizes, int n_in,
                              void* d_out, int out_size) {
    const float* x      = (const float*)d_in[0];   // (64,256,1024,1)
    const float* cond   = (const float*)d_in[1];   // (64,256)
    const float* w1     = (const float*)d_in[2];   // (64,256)
    const float* w2     = (const float*)d_in[3];   // (4,64)
    const float* weight = (const float*)d_in[4];   // (4,256,256,3,3)
    const float* bias   = (const float*)d_in[5];   // (4,256)
    float* out = (float*)d_out;                    // (64,256,1024,1)

    static int attr_set = 0;
    if (!attr_set) {
        cudaFuncSetAttribute(conv_kernel,
                             cudaFuncAttributeMaxDynamicSharedMemorySize, SM_TOTAL);
        attr_set = 1;
    }

    routing_kernel<<<BATCH, 256>>>(cond, w1, w2, bias);
    mix_kernel<<<(3 * NCB * COUT * CCH) / 256, 256>>>(weight);
    conv_kernel<<<dim3(LEN / TN, COUT / TM, BATCH), 256, SM_TOTAL>>>(x, out);
}

// round 10
// speedup vs baseline: 2.4257x; 2.4257x over previous
#include <cuda_runtime.h>
#include <cuda_fp16.h>
#include <mma.h>
#include <cstdint>

using namespace nvcuda;

// DynamicConv: B=64, CIN=COUT=256, K=4 experts, 3x3 kernel on (L=1024 x 1).
// Width==1 + padding 1 => only kw=1 column contributes: per-batch GEMM
//   C[o,h] = sum_{ci,kh} Wagg[b][o,ci,kh] * x[b][ci,h-1+kh]   (M=256,N=1024,K=768)
// R9: fp16 SINGLE-PASS wmma (norm rel err ~2e-4 < 1e-3), cp.async-staged x,
//     uniform prefetch group stream (A tiles + x chunks), 2 CTAs/SM.

#define BATCH   64
#define CIN     256
#define COUT    256
#define CS      256
#define KEXP    4
#define HIDDEN  64
#define LEN     1024
#define TEMP    30.0f

#define TM      128            // o per CTA
#define TN      128            // h per CTA
#define CCH     64             // ci per K-chunk
#define NCB     (CIN / CCH)    // 4
#define NTILE   (3 * NCB)      // 12

#define ASTR    72             // fp16 A row stride (144 B)
#define BSTR    72             // fp16 B row stride
#define BBSTR   24             // bias tile stride (48 B rows)
#define XW      132            // x_s row width (floats): 0..127 body, 128 R-halo, 129 L-halo

// SMEM layout (bytes)
#define SM_A0    0              // A buf0 128x144 = 18432
#define SM_A1    18432          // A buf1
#define SM_B     36864          // B 136x144 = 19584
#define SM_X     56448          // x_s 64x132x4 = 33792
#define SM_TOTAL 90240
// bias tiles overlay B region (pre-mainloop only)
#define SM_ABH   SM_B
#define SM_BB    (SM_B + 6144)

__device__ float g_att[BATCH * KEXP];
__device__ float g_bmix[BATCH * COUT];
// Wagg fp16: [b][kh][cbi][o(256)][ci(64)]
#define WA_BSTRIDE (3 * NCB * COUT * CCH)   // 196608
__device__ __half g_wa[BATCH * WA_BSTRIDE];

__device__ __forceinline__ uint32_t smem_u32(const void* p) {
    uint32_t a;
    asm("{ .reg .u64 t; cvta.to.shared.u64 t, %1; cvt.u32.u64 %0, t; }" : "=r"(a) : "l"(p));
    return a;
}
__device__ __forceinline__ void cpa16(uint32_t d, const void* s) {
    asm volatile("cp.async.cg.shared.global [%0], [%1], 16;" :: "r"(d), "l"(s));
}

// ---------------------------------------------------------------------------
// Kernel 1: routing MLP + softmax + mixed bias.
// ---------------------------------------------------------------------------
__global__ void routing_kernel(const float* __restrict__ cond,
                               const float* __restrict__ w1,
                               const float* __restrict__ w2,
                               const float* __restrict__ bias) {
    __shared__ float sh[HIDDEN];
    __shared__ float sl[KEXP];
    __shared__ float satt[KEXP];
    const int b = blockIdx.x;
    const int t = threadIdx.x;

    if (t < HIDDEN) {
        const float4* crow = (const float4*)(cond + b * CS);
        const float4* w1r  = (const float4*)(w1 + t * CS);
        float s0 = 0.0f, s1 = 0.0f;
#pragma unroll 8
        for (int i = 0; i < CS / 4; ++i) {
            float4 c4 = crow[i], w4 = w1r[i];
            s0 = fmaf(c4.x, w4.x, fmaf(c4.y, w4.y, s0));
            s1 = fmaf(c4.z, w4.z, fmaf(c4.w, w4.w, s1));
        }
        sh[t] = fmaxf(s0 + s1, 0.0f);
    }
    __syncthreads();
    if (t < KEXP) {
        const float* w2r = w2 + t * HIDDEN;
        float s = 0.0f;
#pragma unroll 8
        for (int i = 0; i < HIDDEN; ++i) s = fmaf(sh[i], w2r[i], s);
        sl[t] = s * (1.0f / TEMP);
    }
    __syncthreads();
    if (t == 0) {
        float m = sl[0];
#pragma unroll
        for (int k = 1; k < KEXP; ++k) m = fmaxf(m, sl[k]);
        float e[KEXP], sum = 0.0f;
#pragma unroll
        for (int k = 0; k < KEXP; ++k) { e[k] = expf(sl[k] - m); sum += e[k]; }
        float inv = 1.0f / sum;
#pragma unroll
        for (int k = 0; k < KEXP; ++k) {
            satt[k] = e[k] * inv;
            g_att[b * KEXP + k] = e[k] * inv;
        }
    }
    __syncthreads();
    {
        float v = 0.0f;
#pragma unroll
        for (int k = 0; k < KEXP; ++k) v = fmaf(satt[k], bias[k * COUT + t], v);
        g_bmix[b * COUT + t] = v;
    }
}

// ---------------------------------------------------------------------------
// Kernel 2: mix experts -> g_wa fp16 [b][kh][cbi][o][ci]
// ---------------------------------------------------------------------------
__global__ void mix_kernel(const float* __restrict__ weight) {
    const int idx = blockIdx.x * 256 + threadIdx.x;
    const int ci  = idx & 63;
    const int o   = (idx >> 6) & 255;
    const int cbi = (idx >> 14) & 3;
    const int kh  = idx >> 16;
    const int cig = cbi * CCH + ci;

    float w4[KEXP];
#pragma unroll
    for (int k = 0; k < KEXP; ++k)
        w4[k] = weight[(((k * COUT + o) * CIN + cig) * 3 + kh) * 3 + 1];

    const size_t obase = (((size_t)kh * NCB + cbi) * COUT + o) * CCH + ci;
    for (int b = 0; b < BATCH; ++b) {
        const float* a = g_att + b * KEXP;
        float v = a[0] * w4[0] + a[1] * w4[1] + a[2] * w4[2] + a[3] * w4[3];
        g_wa[(size_t)b * WA_BSTRIDE + obase] = __float2half_rn(v);
    }
}

// ---------------------------------------------------------------------------
// Kernel 3: wmma fp16 conv. grid (8 h-tiles, 2 o-tiles, 64 b), 256 threads.
// ---------------------------------------------------------------------------
__global__ void __launch_bounds__(256, 2)
conv_kernel(const float* __restrict__ x, float* __restrict__ out) {
    extern __shared__ char smem[];
    const uint32_t sb = smem_u32(smem);
    const int tid = threadIdx.x;
    const int wid = tid >> 5;
    const int lid = tid & 31;
    const int hb  = blockIdx.x * TN;
    const int ob  = blockIdx.y * TM;
    const int b   = blockIdx.z;
    const int wm  = wid >> 1;     // 0..3 -> 32 o-rows
    const int wn  = wid & 1;      // 0..1 -> 64 h-cols

    const float* xb = x + (size_t)b * CIN * LEN;
    float* x_s = (float*)(smem + SM_X);

    // ---- prefetch helpers (cp.async; one commit_group per kh iteration) ----
    auto issue_A = [&](int j) {
        const uint32_t bufoff = (j & 1) ? SM_A1 : SM_A0;
        const int cbi = j / 3;
        const int kh  = j - 3 * cbi;
        const uint4* gs = (const uint4*)(g_wa +
            ((((size_t)b * 3 + kh) * NCB + cbi) * COUT + ob) * CCH);
#pragma unroll
        for (int t = 0; t < 4; ++t) {
            int idx = tid + t * 256;          // 1024 chunks = 128 rows x 8
            int r = idx >> 3, c = idx & 7;
            cpa16(sb + bufoff + r * 144 + c * 16, gs + idx);
        }
    };
    auto issue_X = [&](int cbi) {
#pragma unroll
        for (int t = 0; t < 8; ++t) {
            int idx = tid + t * 256;          // 2048 chunks = 64 rows x 32
            int r = idx >> 5, c = idx & 31;
            cpa16(sb + SM_X + r * (XW * 4) + c * 16,
                  xb + (cbi * CCH + r) * LEN + hb + c * 4);
        }
        if (tid < 128) {                      // halo slots (plain STS)
            int r = tid & 63, side = tid >> 6;
            int h = side ? (hb + 128) : (hb - 1);
            float v = ((unsigned)h < (unsigned)LEN) ? xb[(cbi * CCH + r) * LEN + h] : 0.0f;
            x_s[r * XW + (side ? 128 : 129)] = v;
        }
    };

    issue_A(0);
    issue_X(0);
    asm volatile("cp.async.commit_group;" ::: "memory");

    // ---- accumulators + bias GEMM term (hi/lo exact, single mma pass) ----
    wmma::fragment<wmma::accumulator, 16, 16, 16, float> acc[2][4];
#pragma unroll
    for (int mt = 0; mt < 2; ++mt)
#pragma unroll
        for (int nt = 0; nt < 4; ++nt) wmma::fill_fragment(acc[mt][nt], 0.0f);

    for (int i = tid; i < 12288 / 4; i += 256)
        ((uint32_t*)(smem + SM_ABH))[i] = 0;
    __syncthreads();
    if (tid < 128) {
        float bm = g_bmix[b * COUT + ob + tid];
        __half h = __float2half_rn(bm);
        __half* hA = (__half*)(smem + SM_ABH);
        __half* hB = (__half*)(smem + SM_BB);
        hA[tid * BBSTR + 0] = h;
        hA[tid * BBSTR + 1] = __float2half_rn(bm - __half2float(h));
        hB[tid * BBSTR + 0] = __float2half_rn(1.0f);
        hB[tid * BBSTR + 1] = __float2half_rn(1.0f);
    }
    __syncthreads();
    {
        wmma::fragment<wmma::matrix_a, 16, 16, 16, __half, wmma::row_major> fa;
        wmma::fragment<wmma::matrix_b, 16, 16, 16, __half, wmma::col_major> fb[4];
#pragma unroll
        for (int nt = 0; nt < 4; ++nt)
            wmma::load_matrix_sync(fb[nt],
                (const __half*)(smem + SM_BB) + (wn * 64 + nt * 16) * BBSTR, BBSTR);
#pragma unroll
        for (int mt = 0; mt < 2; ++mt) {
            wmma::load_matrix_sync(fa,
                (const __half*)(smem + SM_ABH) + (wm * 32 + mt * 16) * BBSTR, BBSTR);
#pragma unroll
            for (int nt = 0; nt < 4; ++nt)
                wmma::mma_sync(acc[mt][nt], fa, fb[nt], acc[mt][nt]);
        }
    }
    __syncthreads();           // bias tiles dead -> B region reusable

    asm volatile("cp.async.wait_group 0;" ::: "memory");   // A0 + X0 resident
    __syncthreads();

    // ---- mainloop ----
    for (int cbi = 0; cbi < NCB; ++cbi) {
        // build B tile [n][ci] fp16 from x_s (conflict-free both sides)
        {
            const int nl = lid >> 2, cl = lid & 3;
            for (int job = wid; job < 8 * 17; job += 8) {
                const int cpb  = job / 17;
                const int nblk = job - 17 * cpb;
                const int n  = nblk * 8 + nl;
                const int cp = cpb * 4 + cl;          // ci pair 0..31
                if (n < 130) {
                    const int jj = (n == 0) ? 129 : (n - 1);
                    float v0 = x_s[(2 * cp    ) * XW + jj];
                    float v1 = x_s[(2 * cp + 1) * XW + jj];
                    *(__half2*)(smem + SM_B + n * 144 + cp * 4) =
                        __floats2half2_rn(v0, v1);
                }
            }
        }
        __syncthreads();

        for (int kh = 0; kh < 3; ++kh) {
            const int j = cbi * 3 + kh;
            if (j + 1 < NTILE) issue_A(j + 1);
            if (kh == 1 && cbi + 1 < NCB) issue_X(cbi + 1);
            asm volatile("cp.async.commit_group;" ::: "memory");
            asm volatile("cp.async.wait_group 1;" ::: "memory");   // tile j resident
            __syncthreads();

            const __half* A  = (const __half*)(smem + ((j & 1) ? SM_A1 : SM_A0));
            const __half* Bp = (const __half*)(smem + SM_B);

#pragma unroll
            for (int ks = 0; ks < 4; ++ks) {
                wmma::fragment<wmma::matrix_a, 16, 16, 16, __half, wmma::row_major> fa[2];
                wmma::fragment<wmma::matrix_b, 16, 16, 16, __half, wmma::col_major> fb[4];
#pragma unroll
                for (int mt = 0; mt < 2; ++mt)
                    wmma::load_matrix_sync(fa[mt], A + (wm * 32 + mt * 16) * ASTR + ks * 16, ASTR);
#pragma unroll
                for (int nt = 0; nt < 4; ++nt)
                    wmma::load_matrix_sync(fb[nt], Bp + (wn * 64 + nt * 16 + kh) * BSTR + ks * 16, BSTR);
#pragma unroll
                for (int mt = 0; mt < 2; ++mt)
#pragma unroll
                    for (int nt = 0; nt < 4; ++nt)
                        wmma::mma_sync(acc[mt][nt], fa[mt], fb[nt], acc[mt][nt]);
            }
            __syncthreads();   // frag loads done: A buf free at j+1 issue, B at next cbi
        }
    }

    // ---- epilogue: bias already in acc; direct global store ----
    float* op = out + ((size_t)(b * COUT + ob + wm * 32)) * LEN + hb + wn * 64;
#pragma unroll
    for (int mt = 0; mt < 2; ++mt)
#pragma unroll
        for (int nt = 0; nt < 4; ++nt)
            wmma::store_matrix_sync(op + (size_t)mt * 16 * LEN + nt * 16,
                                    acc[mt][nt], LEN, wmma::mem_row_major);
}

// ---------------------------------------------------------------------------
extern "C" void kernel_launch(void* const* d_in, const int* in_sizes, int n_in,
                              void* d_out, int out_size) {
    const float* x      = (const float*)d_in[0];   // (64,256,1024,1)
    const float* cond   = (const float*)d_in[1];   // (64,256)
    const float* w1     = (const float*)d_in[2];   // (64,256)
    const float* w2     = (const float*)d_in[3];   // (4,64)
    const float* weight = (const float*)d_in[4];   // (4,256,256,3,3)
    const float* bias   = (const float*)d_in[5];   // (4,256)
    float* out = (float*)d_out;                    // (64,256,1024,1)

    static int attr_set = 0;
    if (!attr_set) {
        cudaFuncSetAttribute(conv_kernel,
                             cudaFuncAttributeMaxDynamicSharedMemorySize, SM_TOTAL);
        attr_set = 1;
    }

    routing_kernel<<<BATCH, 256>>>(cond, w1, w2, bias);
    mix_kernel<<<(3 * NCB * COUT * CCH) / 256, 256>>>(weight);
    conv_kernel<<<dim3(LEN / TN, COUT / TM, BATCH), 256, SM_TOTAL>>>(x, out);
}

// round 11
// speedup vs baseline: 2.4437x; 1.0074x over previous
#include <cuda_runtime.h>
#include <cuda_fp16.h>
#include <mma.h>
#include <cstdint>

using namespace nvcuda;

// DynamicConv: B=64, CIN=COUT=256, K=4 experts, 3x3 kernel on (L=1024 x 1).
// Width==1 + padding 1 => only kw=1 column contributes: per-batch GEMM
//   C[o,h] = sum_{ci,kh} Wagg[b][o,ci,kh] * x[b][ci,h-1+kh]   (M=256,N=1024,K=768)
// R10: fp16 single-pass wmma + TRIPLE-buffered A cp.async pipeline
//      (wait_group 2 -> two MMA-tiles of latency cover), 2 CTAs/SM.

#define BATCH   64
#define CIN     256
#define COUT    256
#define CS      256
#define KEXP    4
#define HIDDEN  64
#define LEN     1024
#define TEMP    30.0f

#define TM      128            // o per CTA
#define TN      128            // h per CTA
#define CCH     64             // ci per K-chunk
#define NCB     (CIN / CCH)    // 4
#define NTILE   (3 * NCB)      // 12

#define ASTR    72             // fp16 A row stride (144 B)
#define BSTR    72             // fp16 B row stride
#define BBSTR   24             // bias tile stride
#define XW      132            // x_s row width (floats): 0..127 body, 128 R-halo, 129 L-halo

// SMEM layout (bytes)
#define SM_A0    0              // A bufs: 3 x 128x144 = 3 x 18432
#define SM_ABUF(i) ((uint32_t)(18432u * (i)))
#define SM_B     55296          // B 136x144 = 19584
#define SM_X     74880          // x_s 64x132x4 = 33792
#define SM_TOTAL 108672
// bias tiles overlay B region (pre-mainloop only)
#define SM_ABH   SM_B
#define SM_BB    (SM_B + 6144)

__device__ float g_att[BATCH * KEXP];
__device__ float g_bmix[BATCH * COUT];
// Wagg fp16: [b][kh][cbi][o(256)][ci(64)]
#define WA_BSTRIDE (3 * NCB * COUT * CCH)   // 196608
__device__ __half g_wa[BATCH * WA_BSTRIDE];

__device__ __forceinline__ uint32_t smem_u32(const void* p) {
    uint32_t a;
    asm("{ .reg .u64 t; cvta.to.shared.u64 t, %1; cvt.u32.u64 %0, t; }" : "=r"(a) : "l"(p));
    return a;
}
__device__ __forceinline__ void cpa16(uint32_t d, const void* s) {
    asm volatile("cp.async.cg.shared.global [%0], [%1], 16;" :: "r"(d), "l"(s));
}
#define CP_COMMIT()  asm volatile("cp.async.commit_group;" ::: "memory")
#define CP_WAIT(n)   asm volatile("cp.async.wait_group %0;" :: "n"(n) : "memory")

// ---------------------------------------------------------------------------
// Kernel 1: routing MLP + softmax + mixed bias.
// ---------------------------------------------------------------------------
__global__ void routing_kernel(const float* __restrict__ cond,
                               const float* __restrict__ w1,
                               const float* __restrict__ w2,
                               const float* __restrict__ bias) {
    __shared__ float sh[HIDDEN];
    __shared__ float sl[KEXP];
    __shared__ float satt[KEXP];
    const int b = blockIdx.x;
    const int t = threadIdx.x;

    if (t < HIDDEN) {
        const float4* crow = (const float4*)(cond + b * CS);
        const float4* w1r  = (const float4*)(w1 + t * CS);
        float s0 = 0.0f, s1 = 0.0f;
#pragma unroll 8
        for (int i = 0; i < CS / 4; ++i) {
            float4 c4 = crow[i], w4 = w1r[i];
            s0 = fmaf(c4.x, w4.x, fmaf(c4.y, w4.y, s0));
            s1 = fmaf(c4.z, w4.z, fmaf(c4.w, w4.w, s1));
        }
        sh[t] = fmaxf(s0 + s1, 0.0f);
    }
    __syncthreads();
    if (t < KEXP) {
        const float* w2r = w2 + t * HIDDEN;
        float s = 0.0f;
#pragma unroll 8
        for (int i = 0; i < HIDDEN; ++i) s = fmaf(sh[i], w2r[i], s);
        sl[t] = s * (1.0f / TEMP);
    }
    __syncthreads();
    if (t == 0) {
        float m = sl[0];
#pragma unroll
        for (int k = 1; k < KEXP; ++k) m = fmaxf(m, sl[k]);
        float e[KEXP], sum = 0.0f;
#pragma unroll
        for (int k = 0; k < KEXP; ++k) { e[k] = expf(sl[k] - m); sum += e[k]; }
        float inv = 1.0f / sum;
#pragma unroll
        for (int k = 0; k < KEXP; ++k) {
            satt[k] = e[k] * inv;
            g_att[b * KEXP + k] = e[k] * inv;
        }
    }
    __syncthreads();
    {
        float v = 0.0f;
#pragma unroll
        for (int k = 0; k < KEXP; ++k) v = fmaf(satt[k], bias[k * COUT + t], v);
        g_bmix[b * COUT + t] = v;
    }
}

// ---------------------------------------------------------------------------
// Kernel 2: mix experts -> g_wa fp16 [b][kh][cbi][o][ci]. Thread = ci-pair.
// ---------------------------------------------------------------------------
__global__ void mix_kernel(const float* __restrict__ weight) {
    const int idx = blockIdx.x * 256 + threadIdx.x;   // 0 .. 3*4*256*32-1
    const int cp  = idx & 31;                         // ci pair
    const int o   = (idx >> 5) & 255;
    const int cbi = (idx >> 13) & 3;
    const int kh  = idx >> 15;                        // 0..2
    const int ci0 = cbi * CCH + 2 * cp;

    float wa[KEXP], wb[KEXP];
#pragma unroll
    for (int k = 0; k < KEXP; ++k) {
        const float* wp = weight + (((size_t)(k * COUT + o) * CIN + ci0) * 3 + kh) * 3 + 1;
        wa[k] = wp[0];
        wb[k] = wp[9];        // ci0+1 : stride 3*3
    }

    const size_t obase = ((((size_t)kh * NCB + cbi) * COUT + o) * CCH + 2 * cp);
    for (int b = 0; b < BATCH; ++b) {
        const float* a = g_att + b * KEXP;
        float v0 = a[0] * wa[0] + a[1] * wa[1] + a[2] * wa[2] + a[3] * wa[3];
        float v1 = a[0] * wb[0] + a[1] * wb[1] + a[2] * wb[2] + a[3] * wb[3];
        *(__half2*)(g_wa + (size_t)b * WA_BSTRIDE + obase) = __floats2half2_rn(v0, v1);
    }
}

// ---------------------------------------------------------------------------
// Kernel 3: wmma fp16 conv. grid (8 h-tiles, 2 o-tiles, 64 b), 256 threads.
// Triple-buffered A, 2-deep cp.async pipeline.
// ---------------------------------------------------------------------------
__global__ void __launch_bounds__(256, 2)
conv_kernel(const float* __restrict__ x, float* __restrict__ out) {
    extern __shared__ char smem[];
    const uint32_t sb = smem_u32(smem);
    const int tid = threadIdx.x;
    const int wid = tid >> 5;
    const int lid = tid & 31;
    const int hb  = blockIdx.x * TN;
    const int ob  = blockIdx.y * TM;
    const int b   = blockIdx.z;
    const int wm  = wid >> 1;     // 0..3 -> 32 o-rows
    const int wn  = wid & 1;      // 0..1 -> 64 h-cols

    const float* xb = x + (size_t)b * CIN * LEN;
    float* x_s = (float*)(smem + SM_X);

    auto issue_A = [&](int j) {
        const uint32_t bufoff = SM_ABUF(j % 3);
        const int cbi = j / 3;
        const int kh  = j - 3 * cbi;
        const uint4* gs = (const uint4*)(g_wa +
            ((((size_t)b * 3 + kh) * NCB + cbi) * COUT + ob) * CCH);
#pragma unroll
        for (int t = 0; t < 4; ++t) {
            int idx = tid + t * 256;          // 1024 chunks = 128 rows x 8
            int r = idx >> 3, c = idx & 7;
            cpa16(sb + bufoff + r * 144 + c * 16, gs + idx);
        }
    };
    auto issue_X = [&](int cbi) {
#pragma unroll
        for (int t = 0; t < 8; ++t) {
            int idx = tid + t * 256;          // 2048 chunks = 64 rows x 32
            int r = idx >> 5, c = idx & 31;
            cpa16(sb + SM_X + r * (XW * 4) + c * 16,
                  xb + (cbi * CCH + r) * LEN + hb + c * 4);
        }
        if (tid < 128) {                      // halo slots (plain STS)
            int r = tid & 63, side = tid >> 6;
            int h = side ? (hb + 128) : (hb - 1);
            float v = ((unsigned)h < (unsigned)LEN) ? xb[(cbi * CCH + r) * LEN + h] : 0.0f;
            x_s[r * XW + (side ? 128 : 129)] = v;
        }
    };

    // prologue groups: g0={A0,X0}, g1={A1}
    issue_A(0);
    issue_X(0);
    CP_COMMIT();
    issue_A(1);
    CP_COMMIT();

    // ---- accumulators + exact-bias K=16 GEMM term (tiles overlay B region) ----
    wmma::fragment<wmma::accumulator, 16, 16, 16, float> acc[2][4];
#pragma unroll
    for (int mt = 0; mt < 2; ++mt)
#pragma unroll
        for (int nt = 0; nt < 4; ++nt) wmma::fill_fragment(acc[mt][nt], 0.0f);

    for (int i = tid; i < 12288 / 4; i += 256)
        ((uint32_t*)(smem + SM_ABH))[i] = 0;
    __syncthreads();
    if (tid < 128) {
        float bm = g_bmix[b * COUT + ob + tid];
        __half h = __float2half_rn(bm);
        __half* hA = (__half*)(smem + SM_ABH);
        __half* hB = (__half*)(smem + SM_BB);
        hA[tid * BBSTR + 0] = h;
        hA[tid * BBSTR + 1] = __float2half_rn(bm - __half2float(h));
        hB[tid * BBSTR + 0] = __float2half_rn(1.0f);
        hB[tid * BBSTR + 1] = __float2half_rn(1.0f);
    }
    __syncthreads();
    {
        wmma::fragment<wmma::matrix_a, 16, 16, 16, __half, wmma::row_major> fa;
        wmma::fragment<wmma::matrix_b, 16, 16, 16, __half, wmma::col_major> fb[4];
#pragma unroll
        for (int nt = 0; nt < 4; ++nt)
            wmma::load_matrix_sync(fb[nt],
                (const __half*)(smem + SM_BB) + (wn * 64 + nt * 16) * BBSTR, BBSTR);
#pragma unroll
        for (int mt = 0; mt < 2; ++mt) {
            wmma::load_matrix_sync(fa,
                (const __half*)(smem + SM_ABH) + (wm * 32 + mt * 16) * BBSTR, BBSTR);
#pragma unroll
            for (int nt = 0; nt < 4; ++nt)
                wmma::mma_sync(acc[mt][nt], fa, fb[nt], acc[mt][nt]);
        }
    }
    __syncthreads();           // bias tiles dead -> B region reusable

    CP_WAIT(1);                // g0 done: A0 + X0 resident (g1 may pend)
    __syncthreads();

    // ---- mainloop ----
    for (int cbi = 0; cbi < NCB; ++cbi) {
        // build B tile [n][ci] fp16 from x_s (conflict-free both sides)
        {
            const int nl = lid >> 2, cl = lid & 3;
            for (int job = wid; job < 8 * 17; job += 8) {
                const int cpb  = job / 17;
                const int nblk = job - 17 * cpb;
                const int n  = nblk * 8 + nl;
                const int cp = cpb * 4 + cl;          // ci pair 0..31
                if (n < 130) {
                    const int jj = (n == 0) ? 129 : (n - 1);
                    float v0 = x_s[(2 * cp    ) * XW + jj];
                    float v1 = x_s[(2 * cp + 1) * XW + jj];
                    *(__half2*)(smem + SM_B + n * 144 + cp * 4) =
                        __floats2half2_rn(v0, v1);
                }
            }
        }
        __syncthreads();

        for (int kh = 0; kh < 3; ++kh) {
            const int j = cbi * 3 + kh;
            if (j + 2 < NTILE) issue_A(j + 2);
            if (kh == 0 && cbi + 1 < NCB) issue_X(cbi + 1);
            CP_COMMIT();                 // group g_{j+2}
            CP_WAIT(2);                  // groups <= g_j done: A(j) resident
            __syncthreads();

            const __half* A  = (const __half*)(smem + SM_ABUF(j % 3));
            const __half* Bp = (const __half*)(smem + SM_B);

#pragma unroll
            for (int ks = 0; ks < 4; ++ks) {
                wmma::fragment<wmma::matrix_a, 16, 16, 16, __half, wmma::row_major> fa[2];
                wmma::fragment<wmma::matrix_b, 16, 16, 16, __half, wmma::col_major> fb[4];
#pragma unroll
                for (int mt = 0; mt < 2; ++mt)
                    wmma::load_matrix_sync(fa[mt], A + (wm * 32 + mt * 16) * ASTR + ks * 16, ASTR);
#pragma unroll
                for (int nt = 0; nt < 4; ++nt)
                    wmma::load_matrix_sync(fb[nt], Bp + (wn * 64 + nt * 16 + kh) * BSTR + ks * 16, BSTR);
#pragma unroll
                for (int mt = 0; mt < 2; ++mt)
#pragma unroll
                    for (int nt = 0; nt < 4; ++nt)
                        wmma::mma_sync(acc[mt][nt], fa[mt], fb[nt], acc[mt][nt]);
            }
            __syncthreads();   // frag reads done: buf (j)%3 free for issue at j+2... (j+3)
        }
    }

    // ---- epilogue: bias already in acc; direct global store ----
    float* op = out + ((size_t)(b * COUT + ob + wm * 32)) * LEN + hb + wn * 64;
#pragma unroll
    for (int mt = 0; mt < 2; ++mt)
#pragma unroll
        for (int nt = 0; nt < 4; ++nt)
            wmma::store_matrix_sync(op + (size_t)mt * 16 * LEN + nt * 16,
                                    acc[mt][nt], LEN, wmma::mem_row_major);
}

// ---------------------------------------------------------------------------
extern "C" void kernel_launch(void* const* d_in, const int* in_sizes, int n_in,
                              void* d_out, int out_size) {
    const float* x      = (const float*)d_in[0];   // (64,256,1024,1)
    const float* cond   = (const float*)d_in[1];   // (64,256)
    const float* w1     = (const float*)d_in[2];   // (64,256)
    const float* w2     = (const float*)d_in[3];   // (4,64)
    const float* weight = (const float*)d_in[4];   // (4,256,256,3,3)
    const float* bias   = (const float*)d_in[5];   // (4,256)
    float* out = (float*)d_out;                    // (64,256,1024,1)

    static int attr_set = 0;
    if (!attr_set) {
        cudaFuncSetAttribute(conv_kernel,
                             cudaFuncAttributeMaxDynamicSharedMemorySize, SM_TOTAL);
        attr_set = 1;
    }

    routing_kernel<<<BATCH, 256>>>(cond, w1, w2, bias);
    mix_kernel<<<(3 * NCB * COUT * 32) / 256, 256>>>(weight);
    conv_kernel<<<dim3(LEN / TN, COUT / TM, BATCH), 256, SM_TOTAL>>>(x, out);
}